// round 1
// baseline (speedup 1.0000x reference)
#include <cuda_runtime.h>
#include <cuda_bf16.h>

// Problem constants (match reference)
#define GN 512          // number of gaussians
#define IMG_H 512
#define IMG_W 512
#define BLOCK_H 16
#define BLOCK_W 16
#define TILES_X 32
#define TILES_Y 32

// Precomputed per-gaussian parameters (device scratch; no runtime allocation)
__device__ float g_cx[GN];
__device__ float g_cy[GN];
__device__ float g_ca[GN];   // 0.5*ca folded
__device__ float g_cb[GN];   // cb
__device__ float g_cc[GN];   // 0.5*cc folded
__device__ float g_f0[GN];   // feature * opacity
__device__ float g_f1[GN];
__device__ float g_f2[GN];
__device__ unsigned g_bounds[GN]; // tminx | tmaxx<<8 | tminy<<16 | tmaxy<<24

__global__ void precompute_kernel(const float* __restrict__ xyz,
                                  const float* __restrict__ chol,
                                  const float* __restrict__ feat,
                                  const float* __restrict__ opac)
{
    int i = blockIdx.x * blockDim.x + threadIdx.x;
    if (i >= GN) return;

    float mx = tanhf(xyz[2*i + 0]);
    float my = tanhf(xyz[2*i + 1]);

    float l0 = chol[3*i + 0] + 0.5f;
    float l1 = chol[3*i + 1] + 0.0f;
    float l2 = chol[3*i + 2] + 0.5f;

    float cxx = l0 * l0;
    float cxy = l0 * l1;
    float cyy = l1 * l1 + l2 * l2;
    float det = cxx * cyy - cxy * cxy;
    float inv_det = 1.0f / det;
    float ca = cyy * inv_det;
    float cb = -cxy * inv_det;
    float cc = cxx * inv_det;

    float cx = 0.5f * (float)IMG_W * (mx + 1.0f);
    float cy = 0.5f * (float)IMG_H * (my + 1.0f);

    float b  = 0.5f * (cxx + cyy);
    float v1 = b + sqrtf(fmaxf(b * b - det, 0.1f));
    float radius = ceilf(3.0f * sqrtf(v1));

    int tminx = (int)((cx - radius) / (float)BLOCK_W);
    int tmaxx = (int)((cx + radius) / (float)BLOCK_W) + 1;
    int tminy = (int)((cy - radius) / (float)BLOCK_H);
    int tmaxy = (int)((cy + radius) / (float)BLOCK_H) + 1;
    tminx = min(max(tminx, 0), TILES_X);
    tmaxx = min(max(tmaxx, 0), TILES_X);
    tminy = min(max(tminy, 0), TILES_Y);
    tmaxy = min(max(tmaxy, 0), TILES_Y);

    float o = opac[i];

    g_cx[i] = cx;
    g_cy[i] = cy;
    g_ca[i] = 0.5f * ca;
    g_cb[i] = cb;
    g_cc[i] = 0.5f * cc;
    g_f0[i] = feat[3*i + 0] * o;
    g_f1[i] = feat[3*i + 1] * o;
    g_f2[i] = feat[3*i + 2] * o;
    g_bounds[i] = (unsigned)tminx | ((unsigned)tmaxx << 8) |
                  ((unsigned)tminy << 16) | ((unsigned)tmaxy << 24);
}

__global__ __launch_bounds__(256) void render_kernel(float* __restrict__ out)
{
    const int tx = blockIdx.x;   // tile x in [0,32)
    const int ty = blockIdx.y;   // tile y in [0,32)
    const int lx = threadIdx.x;  // [0,16)
    const int ly = threadIdx.y;  // [0,16)
    const int tid = ly * BLOCK_W + lx;

    __shared__ int s_idx[GN];
    __shared__ int s_count;
    if (tid == 0) s_count = 0;
    __syncthreads();

    // Phase A: cull — which gaussians touch this tile (tile-uniform test)
    for (int i = tid; i < GN; i += 256) {
        unsigned b = g_bounds[i];
        int tminx = (int)(b & 0xFF);
        int tmaxx = (int)((b >> 8) & 0xFF);
        int tminy = (int)((b >> 16) & 0xFF);
        int tmaxy = (int)((b >> 24) & 0xFF);
        if (tx >= tminx && tx < tmaxx && ty >= tminy && ty < tmaxy) {
            int p = atomicAdd(&s_count, 1);
            s_idx[p] = i;
        }
    }
    __syncthreads();
    const int cnt = s_count;

    // Phase B: accumulate survivors for this thread's pixel
    const float px = (float)(tx * BLOCK_W + lx);
    const float py = (float)(ty * BLOCK_H + ly);

    float acc0 = 0.0f, acc1 = 0.0f, acc2 = 0.0f;
    for (int k = 0; k < cnt; k++) {
        int i = s_idx[k];  // uniform across block -> broadcast loads
        float dx = g_cx[i] - px;
        float dy = g_cy[i] - py;
        // sigma = 0.5*ca*dx^2 + 0.5*cc*dy^2 + cb*dx*dy
        float sigma = g_ca[i] * dx * dx + g_cc[i] * dy * dy + g_cb[i] * dx * dy;
        float w = __expf(-sigma);
        acc0 += w * g_f0[i];
        acc1 += w * g_f1[i];
        acc2 += w * g_f2[i];
    }

    acc0 = fminf(fmaxf(acc0, 0.0f), 1.0f);
    acc1 = fminf(fmaxf(acc1, 0.0f), 1.0f);
    acc2 = fminf(fmaxf(acc2, 0.0f), 1.0f);

    const int pix = (ty * BLOCK_H + ly) * IMG_W + (tx * BLOCK_W + lx);
    out[0 * IMG_H * IMG_W + pix] = acc0;
    out[1 * IMG_H * IMG_W + pix] = acc1;
    out[2 * IMG_H * IMG_W + pix] = acc2;
}

extern "C" void kernel_launch(void* const* d_in, const int* in_sizes, int n_in,
                              void* d_out, int out_size)
{
    const float* xyz  = (const float*)d_in[0];
    const float* chol = (const float*)d_in[1];
    const float* feat = (const float*)d_in[2];
    const float* opac = (const float*)d_in[3];
    float* out = (float*)d_out;

    precompute_kernel<<<(GN + 255) / 256, 256>>>(xyz, chol, feat, opac);

    dim3 grid(TILES_X, TILES_Y);
    dim3 block(BLOCK_W, BLOCK_H);
    render_kernel<<<grid, block>>>(out);
}

// round 2
// speedup vs baseline: 1.2007x; 1.2007x over previous
#include <cuda_runtime.h>
#include <cuda_bf16.h>

// Problem constants (match reference)
#define GN 512
#define IMG_H 512
#define IMG_W 512
#define BLOCK_H 16
#define BLOCK_W 16
#define TILES_X 32
#define TILES_Y 32

// Fully fused: each CTA (one 16x16 tile) recomputes all 512 gaussians'
// parameters from the raw inputs (2 per thread), culls against its tile
// bounds, compacts survivors into shared memory, then accumulates.
__global__ __launch_bounds__(256) void render_fused_kernel(
    const float* __restrict__ xyz,
    const float* __restrict__ chol,
    const float* __restrict__ feat,
    const float* __restrict__ opac,
    float* __restrict__ out)
{
    const int tx = blockIdx.x;   // tile x
    const int ty = blockIdx.y;   // tile y
    const int lx = threadIdx.x;
    const int ly = threadIdx.y;
    const int tid = ly * BLOCK_W + lx;
    const int lane = tid & 31;

    __shared__ float4 s_p0[GN];  // cx, cy, 0.5*ca, cb
    __shared__ float4 s_p1[GN];  // 0.5*cc, f0*o, f1*o, f2*o
    __shared__ int s_count;
    if (tid == 0) s_count = 0;
    __syncthreads();

    // Phase A: each thread handles gaussians tid and tid+256.
    #pragma unroll
    for (int it = 0; it < 2; it++) {
        const int i = tid + it * 256;

        float2 xy = ((const float2*)xyz)[i];
        float mx = tanhf(xy.x);
        float my = tanhf(xy.y);

        float l0 = chol[3*i + 0] + 0.5f;
        float l1 = chol[3*i + 1];
        float l2 = chol[3*i + 2] + 0.5f;

        float cxx = l0 * l0;
        float cxy = l0 * l1;
        float cyy = l1 * l1 + l2 * l2;
        float det = cxx * cyy - cxy * cxy;
        float inv_det = 1.0f / det;
        float ca = cyy * inv_det;
        float cb = -cxy * inv_det;
        float cc = cxx * inv_det;

        float cx = 0.5f * (float)IMG_W * (mx + 1.0f);
        float cy = 0.5f * (float)IMG_H * (my + 1.0f);

        float b  = 0.5f * (cxx + cyy);
        float v1 = b + sqrtf(fmaxf(b * b - det, 0.1f));
        float radius = ceilf(3.0f * sqrtf(v1));

        int tminx = (int)((cx - radius) * (1.0f / BLOCK_W));
        int tmaxx = (int)((cx + radius) * (1.0f / BLOCK_W)) + 1;
        int tminy = (int)((cy - radius) * (1.0f / BLOCK_H));
        int tmaxy = (int)((cy + radius) * (1.0f / BLOCK_H)) + 1;
        tminx = min(max(tminx, 0), TILES_X);
        tmaxx = min(max(tmaxx, 0), TILES_X);
        tminy = min(max(tminy, 0), TILES_Y);
        tmaxy = min(max(tmaxy, 0), TILES_Y);

        bool pred = (tx >= tminx) && (tx < tmaxx) && (ty >= tminy) && (ty < tmaxy);

        // Warp-aggregated compaction
        unsigned m = __ballot_sync(0xffffffffu, pred);
        int base = 0;
        if (lane == 0) {
            int n = __popc(m);
            base = n ? atomicAdd(&s_count, n) : 0;
        }
        base = __shfl_sync(0xffffffffu, base, 0);
        if (pred) {
            int p = base + __popc(m & ((1u << lane) - 1u));
            float o = opac[i];
            s_p0[p] = make_float4(cx, cy, 0.5f * ca, cb);
            s_p1[p] = make_float4(0.5f * cc,
                                  feat[3*i + 0] * o,
                                  feat[3*i + 1] * o,
                                  feat[3*i + 2] * o);
        }
    }
    __syncthreads();
    const int cnt = s_count;

    // Phase B: accumulate survivors for this thread's pixel.
    const float px = (float)(tx * BLOCK_W + lx);
    const float py = (float)(ty * BLOCK_H + ly);

    float acc0 = 0.0f, acc1 = 0.0f, acc2 = 0.0f;
    for (int k = 0; k < cnt; k++) {
        float4 p0 = s_p0[k];   // broadcast LDS
        float4 p1 = s_p1[k];
        float dx = p0.x - px;
        float dy = p0.y - py;
        float sigma = p0.z * dx * dx + p1.x * dy * dy + p0.w * dx * dy;
        float w = __expf(-sigma);
        acc0 += w * p1.y;
        acc1 += w * p1.z;
        acc2 += w * p1.w;
    }

    acc0 = fminf(fmaxf(acc0, 0.0f), 1.0f);
    acc1 = fminf(fmaxf(acc1, 0.0f), 1.0f);
    acc2 = fminf(fmaxf(acc2, 0.0f), 1.0f);

    const int pix = (ty * BLOCK_H + ly) * IMG_W + (tx * BLOCK_W + lx);
    out[0 * IMG_H * IMG_W + pix] = acc0;
    out[1 * IMG_H * IMG_W + pix] = acc1;
    out[2 * IMG_H * IMG_W + pix] = acc2;
}

extern "C" void kernel_launch(void* const* d_in, const int* in_sizes, int n_in,
                              void* d_out, int out_size)
{
    const float* xyz  = (const float*)d_in[0];
    const float* chol = (const float*)d_in[1];
    const float* feat = (const float*)d_in[2];
    const float* opac = (const float*)d_in[3];
    float* out = (float*)d_out;

    dim3 grid(TILES_X, TILES_Y);
    dim3 block(BLOCK_W, BLOCK_H);
    render_fused_kernel<<<grid, block>>>(xyz, chol, feat, opac, out);
}

// round 3
// speedup vs baseline: 1.2316x; 1.0257x over previous
#include <cuda_runtime.h>
#include <cuda_bf16.h>

// Problem constants (match reference)
#define GN 512
#define IMG_H 512
#define IMG_W 512
#define BLOCK_H 16
#define BLOCK_W 16
#define TILES_X 32
#define TILES_Y 32

// tanh(x) = 1 - 2/(exp(2x)+1); __expf+__fdividef => ~4 instr, ~1e-7 abs err
__device__ __forceinline__ float fast_tanh(float x) {
    return 1.0f - __fdividef(2.0f, __expf(2.0f * x) + 1.0f);
}

__global__ __launch_bounds__(256) void render_fused_kernel(
    const float* __restrict__ xyz,
    const float* __restrict__ chol,
    const float* __restrict__ feat,
    const float* __restrict__ opac,
    float* __restrict__ out)
{
    const int tx = blockIdx.x;   // tile x
    const int ty = blockIdx.y;   // tile y
    const int lx = threadIdx.x;
    const int ly = threadIdx.y;
    const int tid = ly * BLOCK_W + lx;
    const int lane = tid & 31;

    __shared__ float4 s_p0[GN];  // cx, cy, 0.5*ca, cb
    __shared__ float4 s_p1[GN];  // 0.5*cc, f0*o, f1*o, f2*o
    __shared__ int s_count;
    if (tid == 0) s_count = 0;
    __syncthreads();

    // Phase A: cheap cull; full params only for survivors.
    #pragma unroll
    for (int it = 0; it < 2; it++) {
        const int i = tid + it * 256;

        float2 xy = ((const float2*)xyz)[i];
        float l0 = chol[3*i + 0] + 0.5f;
        float l1 = chol[3*i + 1];
        float l2 = chol[3*i + 2] + 0.5f;

        float mx = fast_tanh(xy.x);
        float my = fast_tanh(xy.y);
        float cx = 0.5f * (float)IMG_W * (mx + 1.0f);
        float cy = 0.5f * (float)IMG_H * (my + 1.0f);

        float cxx = l0 * l0;
        float cxy = l0 * l1;
        float cyy = l1 * l1 + l2 * l2;
        float det = cxx * cyy - cxy * cxy;

        float b  = 0.5f * (cxx + cyy);
        float v1 = fmaxf(b * b - det, 0.1f);
        v1 = b + v1 * rsqrtf(v1);                 // b + sqrt(v1)
        float radius = ceilf(3.0f * v1 * rsqrtf(v1));  // ceil(3*sqrt(v1))

        // Unclamped bounds are equivalent to clamped ones for tx,ty in [0,32)
        int tminx = (int)((cx - radius) * (1.0f / BLOCK_W));
        int tmaxx = (int)((cx + radius) * (1.0f / BLOCK_W)) + 1;
        int tminy = (int)((cy - radius) * (1.0f / BLOCK_H));
        int tmaxy = (int)((cy + radius) * (1.0f / BLOCK_H)) + 1;

        bool pred = (tx >= tminx) && (tx < tmaxx) && (ty >= tminy) && (ty < tmaxy);

        // Warp-aggregated compaction
        unsigned m = __ballot_sync(0xffffffffu, pred);
        if (m) {
            int base = 0;
            if (lane == 0) base = atomicAdd(&s_count, __popc(m));
            base = __shfl_sync(0xffffffffu, base, 0);
            if (pred) {
                // Expensive path: only ~2 threads per CTA reach here.
                float inv_det = __fdividef(1.0f, det);
                float ca = cyy * inv_det;
                float cb = -cxy * inv_det;
                float cc = cxx * inv_det;
                float o = opac[i];
                int p = base + __popc(m & ((1u << lane) - 1u));
                s_p0[p] = make_float4(cx, cy, 0.5f * ca, cb);
                s_p1[p] = make_float4(0.5f * cc,
                                      feat[3*i + 0] * o,
                                      feat[3*i + 1] * o,
                                      feat[3*i + 2] * o);
            }
        }
    }
    __syncthreads();
    const int cnt = s_count;

    // Phase B: accumulate survivors for this thread's pixel.
    const float px = (float)(tx * BLOCK_W + lx);
    const float py = (float)(ty * BLOCK_H + ly);

    float acc0 = 0.0f, acc1 = 0.0f, acc2 = 0.0f;
    for (int k = 0; k < cnt; k++) {
        float4 p0 = s_p0[k];   // broadcast LDS
        float4 p1 = s_p1[k];
        float dx = p0.x - px;
        float dy = p0.y - py;
        float sigma = p0.z * dx * dx + p1.x * dy * dy + p0.w * dx * dy;
        float w = __expf(-sigma);
        acc0 += w * p1.y;
        acc1 += w * p1.z;
        acc2 += w * p1.w;
    }

    acc0 = fminf(fmaxf(acc0, 0.0f), 1.0f);
    acc1 = fminf(fmaxf(acc1, 0.0f), 1.0f);
    acc2 = fminf(fmaxf(acc2, 0.0f), 1.0f);

    const int pix = (ty * BLOCK_H + ly) * IMG_W + (tx * BLOCK_W + lx);
    out[0 * IMG_H * IMG_W + pix] = acc0;
    out[1 * IMG_H * IMG_W + pix] = acc1;
    out[2 * IMG_H * IMG_W + pix] = acc2;
}

extern "C" void kernel_launch(void* const* d_in, const int* in_sizes, int n_in,
                              void* d_out, int out_size)
{
    const float* xyz  = (const float*)d_in[0];
    const float* chol = (const float*)d_in[1];
    const float* feat = (const float*)d_in[2];
    const float* opac = (const float*)d_in[3];
    float* out = (float*)d_out;

    dim3 grid(TILES_X, TILES_Y);
    dim3 block(BLOCK_W, BLOCK_H);
    render_fused_kernel<<<grid, block>>>(xyz, chol, feat, opac, out);
}